// round 5
// baseline (speedup 1.0000x reference)
#include <cuda_runtime.h>

#define DIMN 1024
#define NH   16
#define HD   64
#define BATCH 2
#define SEQ  2048
#define NTOK (BATCH*SEQ)   // 4096

// ---------------- scratch (device globals: allocation-free) ----------------
__device__ float g_q[NTOK * DIMN];
__device__ float g_k[NTOK * DIMN];
__device__ float g_v[NTOK * DIMN];
__device__ float g_ctx[NTOK * DIMN];

typedef unsigned long long u64;

// ---------------- packed f32x2 helpers (sm_100+ PTX) ----------------
__device__ __forceinline__ u64 pack2(float x, float y) {
    u64 r; asm("mov.b64 %0, {%1,%2};" : "=l"(r) : "f"(x), "f"(y)); return r;
}
__device__ __forceinline__ void ffma2(u64 &d, u64 a, u64 b) {
    asm("fma.rn.f32x2 %0, %1, %2, %0;" : "+l"(d) : "l"(a), "l"(b));
}
__device__ __forceinline__ u64 mul2(u64 a, u64 b) {
    u64 r; asm("mul.rn.f32x2 %0, %1, %2;" : "=l"(r) : "l"(a), "l"(b)); return r;
}
__device__ __forceinline__ float2 unpack2(u64 v) {
    float lo, hi; asm("mov.b64 {%0,%1}, %2;" : "=f"(lo), "=f"(hi) : "l"(v));
    float2 r; r.x = lo; r.y = hi; return r;
}

// ============================================================================
// SGEMM body: C[M,1024] = A[M,1024] @ W^T[1024,1024] + bias  (both K-major)
// BM=BN=128, BK=16, 256 threads, 8x8 microtile, f32x2 accumulation.
// ============================================================================
__device__ __forceinline__ void gemm_body(const float* __restrict__ A,
                                          const float* __restrict__ W,
                                          const float* __restrict__ bias,
                                          float* __restrict__ C)
{
    __shared__ float As[16 * 128];
    __shared__ float Bs[16 * 128];

    const int tid = threadIdx.x;
    const int m0 = blockIdx.y * 128;
    const int n0 = blockIdx.x * 128;

    // loaders: thread handles rows (lr, lr+64) at k-offset lk..lk+3 of the tile
    const int lr = tid & 63;
    const int lk = (tid >> 6) << 2;          // 0,4,8,12
    const float* Ap  = A + (size_t)(m0 + lr) * DIMN + lk;
    const float* Ap2 = Ap + (size_t)64 * DIMN;
    const float* Wp  = W + (size_t)(n0 + lr) * DIMN + lk;
    const float* Wp2 = Wp + (size_t)64 * DIMN;

    const int tr = tid >> 4;                 // 0..15 -> rows tr*8..tr*8+7
    const int tc = tid & 15;                 // 0..15 -> cols tc*8..tc*8+7

    u64 acc[8][4];
#pragma unroll
    for (int i = 0; i < 8; i++)
#pragma unroll
        for (int j = 0; j < 4; j++) acc[i][j] = 0ull;

    for (int kt = 0; kt < DIMN; kt += 16) {
        float4 a0 = *(const float4*)(Ap  + kt);
        float4 a1 = *(const float4*)(Ap2 + kt);
        float4 b0 = *(const float4*)(Wp  + kt);
        float4 b1 = *(const float4*)(Wp2 + kt);
        __syncthreads();
        // transposed store: As[k][row] (conflict-free: consecutive lr per warp)
        As[(lk+0)*128 + lr] = a0.x;  As[(lk+1)*128 + lr] = a0.y;
        As[(lk+2)*128 + lr] = a0.z;  As[(lk+3)*128 + lr] = a0.w;
        As[(lk+0)*128 + 64 + lr] = a1.x;  As[(lk+1)*128 + 64 + lr] = a1.y;
        As[(lk+2)*128 + 64 + lr] = a1.z;  As[(lk+3)*128 + 64 + lr] = a1.w;
        Bs[(lk+0)*128 + lr] = b0.x;  Bs[(lk+1)*128 + lr] = b0.y;
        Bs[(lk+2)*128 + lr] = b0.z;  Bs[(lk+3)*128 + lr] = b0.w;
        Bs[(lk+0)*128 + 64 + lr] = b1.x;  Bs[(lk+1)*128 + 64 + lr] = b1.y;
        Bs[(lk+2)*128 + 64 + lr] = b1.z;  Bs[(lk+3)*128 + 64 + lr] = b1.w;
        __syncthreads();

#pragma unroll
        for (int k = 0; k < 16; k++) {
            float4 ra0 = *(const float4*)&As[k*128 + tr*8];
            float4 ra1 = *(const float4*)&As[k*128 + tr*8 + 4];
            ulonglong2 rb0 = *(const ulonglong2*)&Bs[k*128 + tc*8];
            ulonglong2 rb1 = *(const ulonglong2*)&Bs[k*128 + tc*8 + 4];
            const u64 bb0 = rb0.x, bb1 = rb0.y, bb2 = rb1.x, bb3 = rb1.y;
            float av[8] = {ra0.x, ra0.y, ra0.z, ra0.w, ra1.x, ra1.y, ra1.z, ra1.w};
#pragma unroll
            for (int i = 0; i < 8; i++) {
                u64 ad = pack2(av[i], av[i]);
                ffma2(acc[i][0], ad, bb0);
                ffma2(acc[i][1], ad, bb1);
                ffma2(acc[i][2], ad, bb2);
                ffma2(acc[i][3], ad, bb3);
            }
        }
    }

    // epilogue: add bias, write two float4 per row
    const float* bp = bias + n0 + tc * 8;
    float bvv[8];
#pragma unroll
    for (int j = 0; j < 8; j++) bvv[j] = bp[j];
#pragma unroll
    for (int i = 0; i < 8; i++) {
        float* Cp = C + (size_t)(m0 + tr*8 + i) * DIMN + n0 + tc*8;
        float2 v0 = unpack2(acc[i][0]);
        float2 v1 = unpack2(acc[i][1]);
        float2 v2 = unpack2(acc[i][2]);
        float2 v3 = unpack2(acc[i][3]);
        float4 o0 = make_float4(v0.x + bvv[0], v0.y + bvv[1], v1.x + bvv[2], v1.y + bvv[3]);
        float4 o1 = make_float4(v2.x + bvv[4], v2.y + bvv[5], v3.x + bvv[6], v3.y + bvv[7]);
        *(float4*)(Cp)     = o0;
        *(float4*)(Cp + 4) = o1;
    }
}

// QKV: grid.z selects projection -> better L2 reuse of x, one launch.
__global__ __launch_bounds__(256) void qkv_kernel(
    const float* __restrict__ x,
    const float* __restrict__ Wq, const float* __restrict__ bq,
    const float* __restrict__ Wk, const float* __restrict__ bk,
    const float* __restrict__ Wv, const float* __restrict__ bv)
{
    const float* W; const float* bb; float* C;
    if (blockIdx.z == 0)      { W = Wq; bb = bq; C = g_q; }
    else if (blockIdx.z == 1) { W = Wk; bb = bk; C = g_k; }
    else                      { W = Wv; bb = bv; C = g_v; }
    gemm_body(x, W, bb, C);
}

__global__ __launch_bounds__(256) void out_kernel(
    const float* __restrict__ Wo, const float* __restrict__ bo,
    float* __restrict__ out)
{
    gemm_body(g_ctx, Wo, bo, out);
}

// ============================================================================
// Flash attention: Br=Bc=64, Dh=64, 256 threads (16x16), online softmax.
// smem: Qt[d][i] (scaled), Kt[d][j], Vs[k][dh] (stride 68), Ps[i][k] (stride 68)
// ============================================================================
#define ATT_SMEM_FLOATS (4096 + 4096 + 64*68 + 64*68)
#define ATT_SMEM_BYTES  (ATT_SMEM_FLOATS * 4)

__global__ __launch_bounds__(256) void attn_kernel()
{
    extern __shared__ float sm[];
    float* Qt = sm;              // 64x64 transposed: Qt[d*64 + i]
    float* Kt = sm + 4096;       // 64x64 transposed: Kt[d*64 + j]
    float* Vs = sm + 8192;       // 64x68 natural:    Vs[k*68 + dh]
    float* Ps = Vs + 64 * 68;    // 64x68:            Ps[i*68 + k]

    const int bh = blockIdx.y;
    const int b  = bh >> 4;
    const int h  = bh & 15;
    const int q0 = blockIdx.x * 64;
    const int tid = threadIdx.x;
    const int ty = tid >> 4;     // 0..15 -> q rows ty*4..ty*4+3
    const int tx = tid & 15;     // 0..15 -> cols  tx*4..tx*4+3

    const float* Qg = g_q + (size_t)(b * SEQ) * DIMN + h * HD;
    const float* Kg = g_k + (size_t)(b * SEQ) * DIMN + h * HD;
    const float* Vg = g_v + (size_t)(b * SEQ) * DIMN + h * HD;

    // load Q tile transposed, fold in 1/sqrt(Dh)
    {
        const int i  = tid & 63;
        const int dc = (tid >> 6) * 16;
        const float* p = Qg + (size_t)(q0 + i) * DIMN + dc;
#pragma unroll
        for (int c = 0; c < 16; c += 4) {
            float4 v = *(const float4*)(p + c);
            Qt[(dc+c+0)*64 + i] = v.x * 0.125f;
            Qt[(dc+c+1)*64 + i] = v.y * 0.125f;
            Qt[(dc+c+2)*64 + i] = v.z * 0.125f;
            Qt[(dc+c+3)*64 + i] = v.w * 0.125f;
        }
    }

    float m[4], l[4];
    u64 o[4][2];
#pragma unroll
    for (int ii = 0; ii < 4; ii++) {
        m[ii] = -1e30f; l[ii] = 0.0f; o[ii][0] = 0ull; o[ii][1] = 0ull;
    }

    for (int kt = 0; kt < SEQ; kt += 64) {
        __syncthreads();   // previous PV done; also makes Qt visible on iter 0
        // K tile transposed (conflict-free scatter: consecutive j per warp)
        {
            const int j  = tid & 63;
            const int dc = (tid >> 6) * 16;
            const float* p = Kg + (size_t)(kt + j) * DIMN + dc;
#pragma unroll
            for (int c = 0; c < 16; c += 4) {
                float4 v = *(const float4*)(p + c);
                Kt[(dc+c+0)*64 + j] = v.x;
                Kt[(dc+c+1)*64 + j] = v.y;
                Kt[(dc+c+2)*64 + j] = v.z;
                Kt[(dc+c+3)*64 + j] = v.w;
            }
        }
        // V tile natural
        {
            const int k  = tid >> 2;
            const int c0 = (tid & 3) * 16;
            const float* p = Vg + (size_t)(kt + k) * DIMN + c0;
#pragma unroll
            for (int c = 0; c < 16; c += 4) {
                float4 v = *(const float4*)(p + c);
                *(float4*)&Vs[k*68 + c0 + c] = v;
            }
        }
        __syncthreads();

        // scores: s[ii][jj] = sum_d Qt[d][ty*4+ii] * Kt[d][tx*4+jj]
        u64 s2[4][2];
#pragma unroll
        for (int ii = 0; ii < 4; ii++) { s2[ii][0] = 0ull; s2[ii][1] = 0ull; }
#pragma unroll 8
        for (int d = 0; d < 64; d++) {
            ulonglong2 kk = *(const ulonglong2*)&Kt[d*64 + tx*4];
            float4 qq = *(const float4*)&Qt[d*64 + ty*4];
            u64 qd;
            qd = pack2(qq.x, qq.x); ffma2(s2[0][0], qd, kk.x); ffma2(s2[0][1], qd, kk.y);
            qd = pack2(qq.y, qq.y); ffma2(s2[1][0], qd, kk.x); ffma2(s2[1][1], qd, kk.y);
            qd = pack2(qq.z, qq.z); ffma2(s2[2][0], qd, kk.x); ffma2(s2[2][1], qd, kk.y);
            qd = pack2(qq.w, qq.w); ffma2(s2[3][0], qd, kk.x); ffma2(s2[3][1], qd, kk.y);
        }

        // online softmax per row (16 tx lanes own one row group; lanes are
        // contiguous 16-lane warp halves, so xor 1/2/4/8 stays in-group)
#pragma unroll
        for (int ii = 0; ii < 4; ii++) {
            float2 a  = unpack2(s2[ii][0]);
            float2 bb = unpack2(s2[ii][1]);
            float rmax = fmaxf(fmaxf(a.x, a.y), fmaxf(bb.x, bb.y));
#pragma unroll
            for (int ofs = 8; ofs > 0; ofs >>= 1)
                rmax = fmaxf(rmax, __shfl_xor_sync(0xffffffffu, rmax, ofs));
            float mn = fmaxf(m[ii], rmax);
            float alpha = __expf(m[ii] - mn);
            m[ii] = mn;
            float p0 = __expf(a.x  - mn);
            float p1 = __expf(a.y  - mn);
            float p2 = __expf(bb.x - mn);
            float p3 = __expf(bb.y - mn);
            float rs = (p0 + p1) + (p2 + p3);
#pragma unroll
            for (int ofs = 8; ofs > 0; ofs >>= 1)
                rs += __shfl_xor_sync(0xffffffffu, rs, ofs);
            l[ii] = l[ii] * alpha + rs;
            u64 av = pack2(alpha, alpha);
            o[ii][0] = mul2(o[ii][0], av);
            o[ii][1] = mul2(o[ii][1], av);
            *(float4*)&Ps[(ty*4 + ii)*68 + tx*4] = make_float4(p0, p1, p2, p3);
        }
        __syncthreads();

        // O += P @ V : o[ii][dh-pairs] over k
#pragma unroll 8
        for (int k = 0; k < 64; k++) {
            ulonglong2 vv = *(const ulonglong2*)&Vs[k*68 + tx*4];
#pragma unroll
            for (int ii = 0; ii < 4; ii++) {
                float pk = Ps[(ty*4 + ii)*68 + k];
                u64 pd = pack2(pk, pk);
                ffma2(o[ii][0], pd, vv.x);
                ffma2(o[ii][1], pd, vv.y);
            }
        }
    }

    // epilogue: ctx[b, q0+i, h*64 + dh] = O / l
    float* Op = g_ctx + (size_t)(b * SEQ + q0) * DIMN + h * HD;
#pragma unroll
    for (int ii = 0; ii < 4; ii++) {
        float inv = 1.0f / l[ii];
        float2 a = unpack2(o[ii][0]);
        float2 c = unpack2(o[ii][1]);
        float4 r = make_float4(a.x * inv, a.y * inv, c.x * inv, c.y * inv);
        *(float4*)(Op + (size_t)(ty*4 + ii) * DIMN + tx*4) = r;
    }
}

// ============================================================================
extern "C" void kernel_launch(void* const* d_in, const int* in_sizes, int n_in,
                              void* d_out, int out_size)
{
    (void)in_sizes; (void)n_in; (void)out_size;
    const float* x  = (const float*)d_in[0];
    const float* Wq = (const float*)d_in[1];
    const float* bq = (const float*)d_in[2];
    const float* Wk = (const float*)d_in[3];
    const float* bk = (const float*)d_in[4];
    const float* Wv = (const float*)d_in[5];
    const float* bv = (const float*)d_in[6];
    const float* Wo = (const float*)d_in[7];
    const float* bo = (const float*)d_in[8];
    float* out = (float*)d_out;

    cudaFuncSetAttribute(attn_kernel,
                         cudaFuncAttributeMaxDynamicSharedMemorySize,
                         ATT_SMEM_BYTES);

    dim3 gqkv(DIMN / 128, NTOK / 128, 3);
    qkv_kernel<<<gqkv, 256>>>(x, Wq, bq, Wk, bk, Wv, bv);

    dim3 gatt(SEQ / 64, BATCH * NH);
    attn_kernel<<<gatt, 256, ATT_SMEM_BYTES>>>();

    dim3 gout(DIMN / 128, NTOK / 128);
    out_kernel<<<gout, 256>>>(Wo, bo, out);
}